// round 7
// baseline (speedup 1.0000x reference)
#include <cuda_runtime.h>
#include <cuda_fp16.h>
#include <cstdint>

#define NB 64
#define NT 2048
#define NM 1024
#define NA 512
#define NQ 1024

#define BM 64             // t-rows per CTA
#define KC 32             // k per stage (fp16: 2 MMA k-steps)
#define NCHUNK (NM / KC)  // 32
#define RS 20             // smem row stride in uints (half2): conflict-free, 16B-aligned
#define NBST 4            // B stages (ring)

#define A_ST (BM * RS)                   // 1280 uints per A stage
#define B_ST (NA * RS)                   // 10240 uints per B stage
#define OFF_A 0
#define OFF_B (2 * A_ST)                 // 2560
#define OFF_WQ (OFF_B + NBST * B_ST)     // floats from here
#define OFF_WV (OFF_WQ + NA)
#define OFF_SP (OFF_WV + NA)
#define SMEM_WORDS (OFF_SP + 16 * 64)
#define SMEM_SZ (SMEM_WORDS * 4)         // ~178 KB

__device__ float g_wq[NB * NA];
__device__ uint32_t g_wm_h[NA * NM / 2];   // Wm as half2 pairs, [a][k/2]
__device__ float g_ctxp[8 * NB * NM];      // context partials [ts][b][m]

__device__ __forceinline__ uint32_t smem_u32(const void* p) {
    uint32_t a;
    asm("{ .reg .u64 t; cvta.to.shared.u64 t, %1; cvt.u32.u64 %0, t; }" : "=r"(a) : "l"(p));
    return a;
}

__device__ __forceinline__ void cpasync16(uint32_t dst, const void* src) {
    asm volatile("cp.async.cg.shared.global [%0], [%1], 16;" :: "r"(dst), "l"(src) : "memory");
}

__device__ __forceinline__ uint32_t pack_h2(float x, float y) {
    __half2 h = __floats2half2_rn(x, y);
    return *(uint32_t*)&h;
}

// fp16-accumulator MMA: D(f16x2 x2) = A*B + D   (full-rate HMMA hypothesis)
__device__ __forceinline__ void mma_f16acc(unsigned& d0, unsigned& d1,
                                           unsigned a0, unsigned a1, unsigned a2, unsigned a3,
                                           unsigned b0, unsigned b1) {
    asm("mma.sync.aligned.m16n8k16.row.col.f16.f16.f16.f16 "
        "{%0,%1},{%2,%3,%4,%5},{%6,%7},{%0,%1};"
        : "+r"(d0), "+r"(d1)
        : "r"(a0), "r"(a1), "r"(a2), "r"(a3), "r"(b0), "r"(b1));
}

// ---------------------------------------------------------------------------
// Kernel 0: convert Wm (fp32) -> g_wm_h (half2 pairs)
// ---------------------------------------------------------------------------
__global__ void cvt_wm_kernel(const float* __restrict__ Wm) {
    int i = blockIdx.x * 256 + threadIdx.x;
    const float4* s = (const float4*)Wm;
    float4 v0 = s[2 * i], v1 = s[2 * i + 1];
    g_wm_h[4 * i + 0] = pack_h2(v0.x, v0.y);
    g_wm_h[4 * i + 1] = pack_h2(v0.z, v0.w);
    g_wm_h[4 * i + 2] = pack_h2(v1.x, v1.y);
    g_wm_h[4 * i + 3] = pack_h2(v1.z, v1.w);
}

// ---------------------------------------------------------------------------
// Kernel 1: wq[b][a] = query[b] . W_query[a]   (fp32 exact, tiny)
// ---------------------------------------------------------------------------
__global__ void wq_kernel(const float* __restrict__ query, const float* __restrict__ Wq) {
    int b = blockIdx.x, a = threadIdx.x;
    const float4* q4 = (const float4*)(query + b * NQ);
    const float4* w4 = (const float4*)(Wq + a * NQ);
    float s = 0.f;
#pragma unroll 8
    for (int k = 0; k < NQ / 4; k++) {
        float4 q = q4[k], w = w4[k];
        s += q.x * w.x + q.y * w.y + q.z * w.z + q.w * w.w;
    }
    g_wq[b * NA + a] = s;
}

// ---------------------------------------------------------------------------
// Kernel 2: fused fp16 mma.sync GEMM (64 x 512 x 1024) + Wv.tanh(wq+wm)
// fp16 accumulators within 2-chunk (K=64) groups, promoted to fp32 per group.
// B: 4-stage cp.async ring (wait_group 2 steady-state); A: 2-chunk reg prefetch.
// ---------------------------------------------------------------------------
__device__ __forceinline__ void issue_B(int c, uint32_t bbuf, int tid) {
    int k2 = c * (KC / 2);                    // uint offset within row
#pragma unroll
    for (int i = 0; i < 4; i++) {             // 512 rows x 4 x 16B
        int e = tid + i * 512;
        int row = e >> 2, c16 = e & 3;
        cpasync16(bbuf + (row * RS + c16 * 4) * 4,
                  g_wm_h + (size_t)row * (NM / 2) + k2 + c16 * 4);
    }
    asm volatile("cp.async.commit_group;" ::: "memory");
}

__global__ __launch_bounds__(512, 1) void score_kernel(
    const float* __restrict__ mem, const float* __restrict__ Wv,
    float* __restrict__ scores)
{
    extern __shared__ __align__(16) uint32_t smem[];
    uint32_t sbase = smem_u32(smem);
    float* wqs = (float*)(smem + OFF_WQ);
    float* wvs = (float*)(smem + OFF_WV);
    float* spr = (float*)(smem + OFF_SP);

    int tid = threadIdx.x, wid = tid >> 5, lane = tid & 31;
    int g = lane >> 2, tg = lane & 3;
    int b = blockIdx.y, t0 = blockIdx.x * BM;

    for (int i = tid; i < NA; i += 512) {
        wqs[i] = g_wq[b * NA + i];
        wvs[i] = Wv[i];
    }

    const float* Ag = mem + ((size_t)b * NT + t0) * NM;
    const int arow = tid >> 3, ac4 = tid & 7;   // A: 64 rows x 8 float4

    float facc[4][4][4];        // persistent fp32 accumulators
#pragma unroll
    for (int mf = 0; mf < 4; mf++)
#pragma unroll
        for (int j = 0; j < 4; j++)
#pragma unroll
            for (int q = 0; q < 4; q++) facc[mf][j][q] = 0.f;

    unsigned acch[4][4][2];     // fp16x2 group accumulators

    // prologue: A two chunks deep in regs; B three stages deep in smem
    float4 ar0 = *(const float4*)(Ag + (size_t)arow * NM + ac4 * 4);            // A(0)
    float4 ar1 = *(const float4*)(Ag + (size_t)arow * NM + KC + ac4 * 4);       // A(1)
    issue_B(0, sbase + (OFF_B + 0 * B_ST) * 4, tid);
    issue_B(1, sbase + (OFF_B + 1 * B_ST) * 4, tid);
    issue_B(2, sbase + (OFF_B + 2 * B_ST) * 4, tid);

    for (int c = 0; c < NCHUNK; c++) {
        // guarantee B(c) landed: committed = B0..B(c+2)  ->  allow 2 pending
        if (c < NCHUNK - 2)      asm volatile("cp.async.wait_group 2;" ::: "memory");
        else if (c < NCHUNK - 1) asm volatile("cp.async.wait_group 1;" ::: "memory");
        else                     asm volatile("cp.async.wait_group 0;" ::: "memory");
        // store A(c) from regs (fp16)
        {
            uint32_t* Ab = smem + OFF_A + (c & 1) * A_ST;
            uint2 u;
            u.x = pack_h2(ar0.x, ar0.y);
            u.y = pack_h2(ar0.z, ar0.w);
            *(uint2*)(Ab + arow * RS + ac4 * 2) = u;
        }
        __syncthreads();   // B(c)+A(c) visible; all warps done with stage (c-1)%4 and A(c-1)
        ar0 = ar1;
        if (c < NCHUNK - 2)
            ar1 = *(const float4*)(Ag + (size_t)arow * NM + (c + 2) * KC + ac4 * 4);
        if (c < NCHUNK - 3)
            issue_B(c + 3, sbase + (OFF_B + ((c + 3) % NBST) * B_ST) * 4, tid);

        if ((c & 1) == 0) {   // new K=64 group: zero fp16 accumulators
#pragma unroll
            for (int mf = 0; mf < 4; mf++)
#pragma unroll
                for (int j = 0; j < 4; j++) { acch[mf][j][0] = 0u; acch[mf][j][1] = 0u; }
        }

        const uint32_t* A  = smem + OFF_A + (c & 1) * A_ST;
        const uint32_t* Bw = smem + OFF_B + (c % NBST) * B_ST + (wid * 32) * RS;
#pragma unroll
        for (int ks = 0; ks < 2; ks++) {
            int ko = ks * 8;   // uint offset for this k16 step
            unsigned af[4][4];
#pragma unroll
            for (int mf = 0; mf < 4; mf++) {
                af[mf][0] = A[(mf * 16 + g) * RS + ko + tg];
                af[mf][1] = A[(mf * 16 + 8 + g) * RS + ko + tg];
                af[mf][2] = A[(mf * 16 + g) * RS + ko + tg + 4];
                af[mf][3] = A[(mf * 16 + 8 + g) * RS + ko + tg + 4];
            }
#pragma unroll
            for (int j = 0; j < 4; j++) {
                unsigned b0 = Bw[(j * 8 + g) * RS + ko + tg];
                unsigned b1 = Bw[(j * 8 + g) * RS + ko + tg + 4];
#pragma unroll
                for (int mf = 0; mf < 4; mf++)
                    mma_f16acc(acch[mf][j][0], acch[mf][j][1],
                               af[mf][0], af[mf][1], af[mf][2], af[mf][3], b0, b1);
            }
        }

        if ((c & 1) == 1) {   // group done: promote fp16 partials to fp32
#pragma unroll
            for (int mf = 0; mf < 4; mf++)
#pragma unroll
                for (int j = 0; j < 4; j++) {
                    float2 lo = __half22float2(*(__half2*)&acch[mf][j][0]);
                    float2 hi = __half22float2(*(__half2*)&acch[mf][j][1]);
                    facc[mf][j][0] += lo.x;
                    facc[mf][j][1] += lo.y;
                    facc[mf][j][2] += hi.x;
                    facc[mf][j][3] += hi.y;
                }
        }
    }

    // epilogue: partial score rows for this warp's 32 cols
    float p0[4], p1[4];
#pragma unroll
    for (int mf = 0; mf < 4; mf++) { p0[mf] = 0.f; p1[mf] = 0.f; }
#pragma unroll
    for (int mf = 0; mf < 4; mf++)
#pragma unroll
        for (int j = 0; j < 4; j++) {
            int a0 = wid * 32 + j * 8 + 2 * tg;
            float w0 = wvs[a0], w1 = wvs[a0 + 1];
            float q0 = wqs[a0], q1 = wqs[a0 + 1];
            p0[mf] += w0 * tanhf(q0 + facc[mf][j][0]) + w1 * tanhf(q1 + facc[mf][j][1]);
            p1[mf] += w0 * tanhf(q0 + facc[mf][j][2]) + w1 * tanhf(q1 + facc[mf][j][3]);
        }
#pragma unroll
    for (int mf = 0; mf < 4; mf++) {
        p0[mf] += __shfl_xor_sync(0xffffffffu, p0[mf], 1);
        p0[mf] += __shfl_xor_sync(0xffffffffu, p0[mf], 2);
        p1[mf] += __shfl_xor_sync(0xffffffffu, p1[mf], 1);
        p1[mf] += __shfl_xor_sync(0xffffffffu, p1[mf], 2);
    }
    if (tg == 0) {
#pragma unroll
        for (int mf = 0; mf < 4; mf++) {
            spr[wid * 64 + mf * 16 + g]     = p0[mf];
            spr[wid * 64 + mf * 16 + 8 + g] = p1[mf];
        }
    }
    __syncthreads();
    if (tid < BM) {
        float s = 0.f;
#pragma unroll
        for (int w = 0; w < 16; w++) s += spr[w * 64 + tid];
        scores[b * NT + t0 + tid] = s;
    }
}

// ---------------------------------------------------------------------------
// Kernel 3: in-place softmax over T per batch row
// ---------------------------------------------------------------------------
__global__ void softmax_kernel(float* __restrict__ sc) {
    int b = blockIdx.x;
    float* row = sc + b * NT;
    int tid = threadIdx.x;  // 256
    __shared__ float red[8];
    float v[8];
    float m = -3.0e38f;
#pragma unroll
    for (int i = 0; i < 8; i++) { v[i] = row[tid + 256 * i]; m = fmaxf(m, v[i]); }
#pragma unroll
    for (int o = 16; o; o >>= 1) m = fmaxf(m, __shfl_xor_sync(0xffffffffu, m, o));
    if ((tid & 31) == 0) red[tid >> 5] = m;
    __syncthreads();
    m = red[0];
#pragma unroll
    for (int w = 1; w < 8; w++) m = fmaxf(m, red[w]);
    __syncthreads();
    float s = 0.f;
#pragma unroll
    for (int i = 0; i < 8; i++) { v[i] = expf(v[i] - m); s += v[i]; }
#pragma unroll
    for (int o = 16; o; o >>= 1) s += __shfl_xor_sync(0xffffffffu, s, o);
    if ((tid & 31) == 0) red[tid >> 5] = s;
    __syncthreads();
    s = 0.f;
#pragma unroll
    for (int w = 0; w < 8; w++) s += red[w];
    float inv = 1.f / s;
#pragma unroll
    for (int i = 0; i < 8; i++) row[tid + 256 * i] = v[i] * inv;
}

// ---------------------------------------------------------------------------
// Kernel 4: context partials over 8 T-slices (deterministic)
// ---------------------------------------------------------------------------
__global__ __launch_bounds__(128) void context_part_kernel(
    const float* __restrict__ mem, const float* __restrict__ alpha)
{
    __shared__ float al[256];
    int b = blockIdx.z, ts = blockIdx.y;
    int m0 = blockIdx.x * 512 + threadIdx.x * 4;
    al[threadIdx.x]       = alpha[b * NT + ts * 256 + threadIdx.x];
    al[threadIdx.x + 128] = alpha[b * NT + ts * 256 + 128 + threadIdx.x];
    __syncthreads();
    const float* mp = mem + ((size_t)b * NT + ts * 256) * NM + m0;
    float4 acc0 = {0.f, 0.f, 0.f, 0.f}, acc1 = {0.f, 0.f, 0.f, 0.f};
#pragma unroll 4
    for (int t = 0; t < 256; t += 2) {
        float a0 = al[t], a1 = al[t + 1];
        float4 v0 = *(const float4*)(mp + (size_t)t * NM);
        float4 v1 = *(const float4*)(mp + (size_t)(t + 1) * NM);
        acc0.x += a0 * v0.x; acc0.y += a0 * v0.y; acc0.z += a0 * v0.z; acc0.w += a0 * v0.w;
        acc1.x += a1 * v1.x; acc1.y += a1 * v1.y; acc1.z += a1 * v1.z; acc1.w += a1 * v1.w;
    }
    float4 out;
    out.x = acc0.x + acc1.x; out.y = acc0.y + acc1.y;
    out.z = acc0.z + acc1.z; out.w = acc0.w + acc1.w;
    *(float4*)(g_ctxp + ((size_t)ts * NB + b) * NM + m0) = out;
}

__global__ void ctx_reduce_kernel(float* __restrict__ ctx) {
    int b = blockIdx.x, m = threadIdx.x;
    float s = 0.f;
#pragma unroll
    for (int ts = 0; ts < 8; ts++)
        s += g_ctxp[((size_t)ts * NB + b) * NM + m];
    ctx[b * NM + m] = s;
}

// ---------------------------------------------------------------------------
extern "C" void kernel_launch(void* const* d_in, const int* in_sizes, int n_in,
                              void* d_out, int out_size) {
    const float* query  = (const float*)d_in[0];
    const float* memory = (const float*)d_in[1];
    const float* Wq     = (const float*)d_in[2];
    const float* Wm     = (const float*)d_in[3];
    const float* Wv     = (const float*)d_in[4];
    float* alpha = (float*)d_out;            // [64, 2048]
    float* ctx   = alpha + NB * NT;          // [64, 1024]

    cvt_wm_kernel<<<256, 256>>>(Wm);
    wq_kernel<<<NB, NA>>>(query, Wq);

    cudaFuncSetAttribute(score_kernel, cudaFuncAttributeMaxDynamicSharedMemorySize, SMEM_SZ);
    score_kernel<<<dim3(NT / BM, NB), 512, SMEM_SZ>>>(memory, Wv, alpha);

    softmax_kernel<<<NB, 256>>>(alpha);
    context_part_kernel<<<dim3(2, 8, NB), 128>>>(memory, alpha);
    ctx_reduce_kernel<<<NB, NM>>>(ctx);
}

// round 8
// speedup vs baseline: 1.7828x; 1.7828x over previous
#include <cuda_runtime.h>
#include <cuda_fp16.h>
#include <cstdint>

#define NB 64
#define NT 2048
#define NM 1024
#define NA 512
#define NQ 1024

#define BM 64             // t-rows per CTA
#define KC 32             // k per stage (fp16: 2 MMA k-steps)
#define NCHUNK (NM / KC)  // 32
#define RS 20             // smem row stride in uints (half2): conflict-free, 16B-aligned
#define NBST 4            // B stages (ring)

#define A_ST (BM * RS)                   // 1280 uints per A stage
#define B_ST (NA * RS)                   // 10240 uints per B stage
#define OFF_A 0
#define OFF_B (2 * A_ST)                 // 2560
#define OFF_WQ (OFF_B + NBST * B_ST)     // floats from here
#define OFF_WV (OFF_WQ + NA)
#define OFF_SP (OFF_WV + NA)
#define SMEM_WORDS (OFF_SP + 16 * 64)
#define SMEM_SZ (SMEM_WORDS * 4)         // ~178 KB

__device__ float g_wq[NB * NA];
__device__ uint32_t g_wm_h[NA * NM / 2];   // Wm as half2 pairs, [a][k/2]
__device__ float g_ctxp[8 * NB * NM];      // context partials [ts][b][m]

__device__ __forceinline__ uint32_t smem_u32(const void* p) {
    uint32_t a;
    asm("{ .reg .u64 t; cvta.to.shared.u64 t, %1; cvt.u32.u64 %0, t; }" : "=r"(a) : "l"(p));
    return a;
}

__device__ __forceinline__ void cpasync16(uint32_t dst, const void* src) {
    asm volatile("cp.async.cg.shared.global [%0], [%1], 16;" :: "r"(dst), "l"(src) : "memory");
}

__device__ __forceinline__ uint32_t pack_h2(float x, float y) {
    __half2 h = __floats2half2_rn(x, y);
    return *(uint32_t*)&h;
}

__device__ __forceinline__ void mma_f16(float& d0, float& d1, float& d2, float& d3,
                                        unsigned a0, unsigned a1, unsigned a2, unsigned a3,
                                        unsigned b0, unsigned b1) {
    asm("mma.sync.aligned.m16n8k16.row.col.f32.f16.f16.f32 "
        "{%0,%1,%2,%3},{%4,%5,%6,%7},{%8,%9},{%0,%1,%2,%3};"
        : "+f"(d0), "+f"(d1), "+f"(d2), "+f"(d3)
        : "r"(a0), "r"(a1), "r"(a2), "r"(a3), "r"(b0), "r"(b1));
}

#define LDMX4(r0, r1, r2, r3, addr) \
    asm volatile("ldmatrix.sync.aligned.m8n8.x4.shared.b16 {%0,%1,%2,%3}, [%4];" \
                 : "=r"(r0), "=r"(r1), "=r"(r2), "=r"(r3) : "r"(addr))

// ---------------------------------------------------------------------------
// Kernel 0: convert Wm (fp32) -> g_wm_h (half2 pairs)
// ---------------------------------------------------------------------------
__global__ void cvt_wm_kernel(const float* __restrict__ Wm) {
    int i = blockIdx.x * 256 + threadIdx.x;
    const float4* s = (const float4*)Wm;
    float4 v0 = s[2 * i], v1 = s[2 * i + 1];
    g_wm_h[4 * i + 0] = pack_h2(v0.x, v0.y);
    g_wm_h[4 * i + 1] = pack_h2(v0.z, v0.w);
    g_wm_h[4 * i + 2] = pack_h2(v1.x, v1.y);
    g_wm_h[4 * i + 3] = pack_h2(v1.z, v1.w);
}

// ---------------------------------------------------------------------------
// Kernel 1: wq[b][a] = query[b] . W_query[a]   (fp32 exact, tiny)
// ---------------------------------------------------------------------------
__global__ void wq_kernel(const float* __restrict__ query, const float* __restrict__ Wq) {
    int b = blockIdx.x, a = threadIdx.x;
    const float4* q4 = (const float4*)(query + b * NQ);
    const float4* w4 = (const float4*)(Wq + a * NQ);
    float s = 0.f;
#pragma unroll 8
    for (int k = 0; k < NQ / 4; k++) {
        float4 q = q4[k], w = w4[k];
        s += q.x * w.x + q.y * w.y + q.z * w.z + q.w * w.w;
    }
    g_wq[b * NA + a] = s;
}

// ---------------------------------------------------------------------------
// Kernel 2: fused fp16 mma.sync GEMM (64 x 512 x 1024) + Wv.tanh(wq+wm)
// fp32 accumulators (R6 structure). Fragment loads via ldmatrix.x4
// (12 per warp/chunk instead of 48 scalar LDS).
// B: 4-stage cp.async ring (wait_group 2 steady); A: 2-chunk reg prefetch.
// ---------------------------------------------------------------------------
__device__ __forceinline__ void issue_B(int c, uint32_t bbuf, int tid) {
    int k2 = c * (KC / 2);                    // uint offset within row
#pragma unroll
    for (int i = 0; i < 4; i++) {             // 512 rows x 4 x 16B
        int e = tid + i * 512;
        int row = e >> 2, c16 = e & 3;
        cpasync16(bbuf + (row * RS + c16 * 4) * 4,
                  g_wm_h + (size_t)row * (NM / 2) + k2 + c16 * 4);
    }
    asm volatile("cp.async.commit_group;" ::: "memory");
}

__global__ __launch_bounds__(512, 1) void score_kernel(
    const float* __restrict__ mem, const float* __restrict__ Wv,
    float* __restrict__ scores)
{
    extern __shared__ __align__(16) uint32_t smem[];
    uint32_t sbase = smem_u32(smem);
    float* wqs = (float*)(smem + OFF_WQ);
    float* wvs = (float*)(smem + OFF_WV);
    float* spr = (float*)(smem + OFF_SP);

    int tid = threadIdx.x, wid = tid >> 5, lane = tid & 31;
    int g = lane >> 2, tg = lane & 3;
    int b = blockIdx.y, t0 = blockIdx.x * BM;

    for (int i = tid; i < NA; i += 512) {
        wqs[i] = g_wq[b * NA + i];
        wvs[i] = Wv[i];
    }

    const float* Ag = mem + ((size_t)b * NT + t0) * NM;
    const int arow = tid >> 3, ac4 = tid & 7;   // A: 64 rows x 8 float4

    // ldmatrix lane-address components (uint offsets within a stage)
    int q8 = lane >> 3, r8 = lane & 7;
    // A x4: r0=(rows 0-7,klo) r1=(rows 8-15,klo) r2=(rows 0-7,khi) r3=(rows 8-15,khi)
    int aoff = ((q8 & 1) * 8 + r8) * RS + (q8 >> 1) * 4;
    // B x4: r0=(j,klo) r1=(j,khi) r2=(j+1,klo) r3=(j+1,khi)
    int boff = ((q8 & 2) * 4 + r8 + wid * 32) * RS + (q8 & 1) * 4;

    float acc[4][4][4];
#pragma unroll
    for (int mf = 0; mf < 4; mf++)
#pragma unroll
        for (int j = 0; j < 4; j++)
#pragma unroll
            for (int qq = 0; qq < 4; qq++) acc[mf][j][qq] = 0.f;

    // prologue: A two chunks deep in regs; B three stages deep in smem
    float4 ar0 = *(const float4*)(Ag + (size_t)arow * NM + ac4 * 4);            // A(0)
    float4 ar1 = *(const float4*)(Ag + (size_t)arow * NM + KC + ac4 * 4);       // A(1)
    issue_B(0, sbase + (OFF_B + 0 * B_ST) * 4, tid);
    issue_B(1, sbase + (OFF_B + 1 * B_ST) * 4, tid);
    issue_B(2, sbase + (OFF_B + 2 * B_ST) * 4, tid);

    for (int c = 0; c < NCHUNK; c++) {
        // guarantee B(c) landed: committed = B0..B(c+2)  ->  allow 2 pending
        if (c < NCHUNK - 2)      asm volatile("cp.async.wait_group 2;" ::: "memory");
        else if (c < NCHUNK - 1) asm volatile("cp.async.wait_group 1;" ::: "memory");
        else                     asm volatile("cp.async.wait_group 0;" ::: "memory");
        // store A(c) from regs (fp16)
        {
            uint32_t* Ab = smem + OFF_A + (c & 1) * A_ST;
            uint2 u;
            u.x = pack_h2(ar0.x, ar0.y);
            u.y = pack_h2(ar0.z, ar0.w);
            *(uint2*)(Ab + arow * RS + ac4 * 2) = u;
        }
        __syncthreads();   // B(c)+A(c) visible; all warps done with stage (c-1)%4 and A(c-1)
        ar0 = ar1;
        if (c < NCHUNK - 2)
            ar1 = *(const float4*)(Ag + (size_t)arow * NM + (c + 2) * KC + ac4 * 4);
        if (c < NCHUNK - 3)
            issue_B(c + 3, sbase + (OFF_B + ((c + 3) % NBST) * B_ST) * 4, tid);

        uint32_t Abase = sbase + (OFF_A + (c & 1) * A_ST + aoff) * 4;
        uint32_t Bbase = sbase + (OFF_B + (c % NBST) * B_ST + boff) * 4;
#pragma unroll
        for (int ks = 0; ks < 2; ks++) {
            int ko4 = ks * 8 * 4;   // byte offset for this k16 step
            unsigned af[4][4];
#pragma unroll
            for (int mf = 0; mf < 4; mf++)
                LDMX4(af[mf][0], af[mf][1], af[mf][2], af[mf][3],
                      Abase + ko4 + mf * 16 * RS * 4);
            unsigned bf[8];
            LDMX4(bf[0], bf[1], bf[2], bf[3], Bbase + ko4);
            LDMX4(bf[4], bf[5], bf[6], bf[7], Bbase + ko4 + 16 * RS * 4);
#pragma unroll
            for (int j = 0; j < 4; j++) {
                unsigned b0 = bf[j * 2], b1 = bf[j * 2 + 1];
#pragma unroll
                for (int mf = 0; mf < 4; mf++)
                    mma_f16(acc[mf][j][0], acc[mf][j][1], acc[mf][j][2], acc[mf][j][3],
                            af[mf][0], af[mf][1], af[mf][2], af[mf][3], b0, b1);
            }
        }
    }

    // epilogue: partial score rows for this warp's 32 cols
    float p0[4], p1[4];
#pragma unroll
    for (int mf = 0; mf < 4; mf++) { p0[mf] = 0.f; p1[mf] = 0.f; }
#pragma unroll
    for (int mf = 0; mf < 4; mf++)
#pragma unroll
        for (int j = 0; j < 4; j++) {
            int a0 = wid * 32 + j * 8 + 2 * tg;
            float w0 = wvs[a0], w1 = wvs[a0 + 1];
            float q0 = wqs[a0], q1 = wqs[a0 + 1];
            p0[mf] += w0 * tanhf(q0 + acc[mf][j][0]) + w1 * tanhf(q1 + acc[mf][j][1]);
            p1[mf] += w0 * tanhf(q0 + acc[mf][j][2]) + w1 * tanhf(q1 + acc[mf][j][3]);
        }
#pragma unroll
    for (int mf = 0; mf < 4; mf++) {
        p0[mf] += __shfl_xor_sync(0xffffffffu, p0[mf], 1);
        p0[mf] += __shfl_xor_sync(0xffffffffu, p0[mf], 2);
        p1[mf] += __shfl_xor_sync(0xffffffffu, p1[mf], 1);
        p1[mf] += __shfl_xor_sync(0xffffffffu, p1[mf], 2);
    }
    if (tg == 0) {
#pragma unroll
        for (int mf = 0; mf < 4; mf++) {
            spr[wid * 64 + mf * 16 + g]     = p0[mf];
            spr[wid * 64 + mf * 16 + 8 + g] = p1[mf];
        }
    }
    __syncthreads();
    if (tid < BM) {
        float s = 0.f;
#pragma unroll
        for (int w = 0; w < 16; w++) s += spr[w * 64 + tid];
        scores[b * NT + t0 + tid] = s;
    }
}

// ---------------------------------------------------------------------------
// Kernel 3: in-place softmax over T per batch row
// ---------------------------------------------------------------------------
__global__ void softmax_kernel(float* __restrict__ sc) {
    int b = blockIdx.x;
    float* row = sc + b * NT;
    int tid = threadIdx.x;  // 256
    __shared__ float red[8];
    float v[8];
    float m = -3.0e38f;
#pragma unroll
    for (int i = 0; i < 8; i++) { v[i] = row[tid + 256 * i]; m = fmaxf(m, v[i]); }
#pragma unroll
    for (int o = 16; o; o >>= 1) m = fmaxf(m, __shfl_xor_sync(0xffffffffu, m, o));
    if ((tid & 31) == 0) red[tid >> 5] = m;
    __syncthreads();
    m = red[0];
#pragma unroll
    for (int w = 1; w < 8; w++) m = fmaxf(m, red[w]);
    __syncthreads();
    float s = 0.f;
#pragma unroll
    for (int i = 0; i < 8; i++) { v[i] = expf(v[i] - m); s += v[i]; }
#pragma unroll
    for (int o = 16; o; o >>= 1) s += __shfl_xor_sync(0xffffffffu, s, o);
    if ((tid & 31) == 0) red[tid >> 5] = s;
    __syncthreads();
    s = 0.f;
#pragma unroll
    for (int w = 0; w < 8; w++) s += red[w];
    float inv = 1.f / s;
#pragma unroll
    for (int i = 0; i < 8; i++) row[tid + 256 * i] = v[i] * inv;
}

// ---------------------------------------------------------------------------
// Kernel 4: context partials over 8 T-slices (deterministic)
// ---------------------------------------------------------------------------
__global__ __launch_bounds__(128) void context_part_kernel(
    const float* __restrict__ mem, const float* __restrict__ alpha)
{
    __shared__ float al[256];
    int b = blockIdx.z, ts = blockIdx.y;
    int m0 = blockIdx.x * 512 + threadIdx.x * 4;
    al[threadIdx.x]       = alpha[b * NT + ts * 256 + threadIdx.x];
    al[threadIdx.x + 128] = alpha[b * NT + ts * 256 + 128 + threadIdx.x];
    __syncthreads();
    const float* mp = mem + ((size_t)b * NT + ts * 256) * NM + m0;
    float4 acc0 = {0.f, 0.f, 0.f, 0.f}, acc1 = {0.f, 0.f, 0.f, 0.f};
#pragma unroll 4
    for (int t = 0; t < 256; t += 2) {
        float a0 = al[t], a1 = al[t + 1];
        float4 v0 = *(const float4*)(mp + (size_t)t * NM);
        float4 v1 = *(const float4*)(mp + (size_t)(t + 1) * NM);
        acc0.x += a0 * v0.x; acc0.y += a0 * v0.y; acc0.z += a0 * v0.z; acc0.w += a0 * v0.w;
        acc1.x += a1 * v1.x; acc1.y += a1 * v1.y; acc1.z += a1 * v1.z; acc1.w += a1 * v1.w;
    }
    float4 out;
    out.x = acc0.x + acc1.x; out.y = acc0.y + acc1.y;
    out.z = acc0.z + acc1.z; out.w = acc0.w + acc1.w;
    *(float4*)(g_ctxp + ((size_t)ts * NB + b) * NM + m0) = out;
}

__global__ void ctx_reduce_kernel(float* __restrict__ ctx) {
    int b = blockIdx.x, m = threadIdx.x;
    float s = 0.f;
#pragma unroll
    for (int ts = 0; ts < 8; ts++)
        s += g_ctxp[((size_t)ts * NB + b) * NM + m];
    ctx[b * NM + m] = s;
}

// ---------------------------------------------------------------------------
extern "C" void kernel_launch(void* const* d_in, const int* in_sizes, int n_in,
                              void* d_out, int out_size) {
    const float* query  = (const float*)d_in[0];
    const float* memory = (const float*)d_in[1];
    const float* Wq     = (const float*)d_in[2];
    const float* Wm     = (const float*)d_in[3];
    const float* Wv     = (const float*)d_in[4];
    float* alpha = (float*)d_out;            // [64, 2048]
    float* ctx   = alpha + NB * NT;          // [64, 1024]

    cvt_wm_kernel<<<256, 256>>>(Wm);
    wq_kernel<<<NB, NA>>>(query, Wq);

    cudaFuncSetAttribute(score_kernel, cudaFuncAttributeMaxDynamicSharedMemorySize, SMEM_SZ);
    score_kernel<<<dim3(NT / BM, NB), 512, SMEM_SZ>>>(memory, Wv, alpha);

    softmax_kernel<<<NB, 256>>>(alpha);
    context_part_kernel<<<dim3(2, 8, NB), 128>>>(memory, alpha);
    ctx_reduce_kernel<<<NB, NM>>>(ctx);
}

// round 9
// speedup vs baseline: 1.8749x; 1.0517x over previous
#include <cuda_runtime.h>
#include <cuda_fp16.h>
#include <cstdint>

#define NB 64
#define NT 2048
#define NM 1024
#define NA 512
#define NQ 1024

#define BM 64             // t-rows per CTA
#define KC 32             // k per stage (fp16: 2 MMA k-steps)
#define NCHUNK (NM / KC)  // 32
#define RS 20             // smem row stride in uints (half2): conflict-free, 16B-aligned
#define NBST 4            // B stages (ring)

#define A_ST (BM * RS)                   // 1280 uints per A stage
#define B_ST (NA * RS)                   // 10240 uints per B stage
#define OFF_A 0
#define OFF_B (2 * A_ST)                 // 2560
#define OFF_WQ (OFF_B + NBST * B_ST)     // floats from here
#define OFF_WV (OFF_WQ + NA)
#define OFF_SP (OFF_WV + NA)
#define OFF_ES (OFF_SP + 16 * 64)        // 64 exp(score) values
#define SMEM_WORDS (OFF_ES + 64)
#define SMEM_SZ (SMEM_WORDS * 4)         // ~178 KB

#define NSLICE (NT / BM)                 // 32 t-slices per batch

__device__ float g_wq[NB * NA];
__device__ uint32_t g_wm_h[NA * NM / 2];        // Wm as half2 pairs, [a][k/2]
__device__ float g_ctxp[NSLICE * NB * NM];      // context partials [slice][b][m] (8 MB)

__device__ __forceinline__ uint32_t smem_u32(const void* p) {
    uint32_t a;
    asm("{ .reg .u64 t; cvta.to.shared.u64 t, %1; cvt.u32.u64 %0, t; }" : "=r"(a) : "l"(p));
    return a;
}

__device__ __forceinline__ void cpasync16(uint32_t dst, const void* src) {
    asm volatile("cp.async.cg.shared.global [%0], [%1], 16;" :: "r"(dst), "l"(src) : "memory");
}

__device__ __forceinline__ uint32_t pack_h2(float x, float y) {
    __half2 h = __floats2half2_rn(x, y);
    return *(uint32_t*)&h;
}

__device__ __forceinline__ void mma_f16(float& d0, float& d1, float& d2, float& d3,
                                        unsigned a0, unsigned a1, unsigned a2, unsigned a3,
                                        unsigned b0, unsigned b1) {
    asm("mma.sync.aligned.m16n8k16.row.col.f32.f16.f16.f32 "
        "{%0,%1,%2,%3},{%4,%5,%6,%7},{%8,%9},{%0,%1,%2,%3};"
        : "+f"(d0), "+f"(d1), "+f"(d2), "+f"(d3)
        : "r"(a0), "r"(a1), "r"(a2), "r"(a3), "r"(b0), "r"(b1));
}

#define LDMX4(r0, r1, r2, r3, addr) \
    asm volatile("ldmatrix.sync.aligned.m8n8.x4.shared.b16 {%0,%1,%2,%3}, [%4];" \
                 : "=r"(r0), "=r"(r1), "=r"(r2), "=r"(r3) : "r"(addr))

// ---------------------------------------------------------------------------
// Kernel 0: convert Wm (fp32) -> g_wm_h (half2 pairs)
// ---------------------------------------------------------------------------
__global__ void cvt_wm_kernel(const float* __restrict__ Wm) {
    int i = blockIdx.x * 256 + threadIdx.x;
    const float4* s = (const float4*)Wm;
    float4 v0 = s[2 * i], v1 = s[2 * i + 1];
    g_wm_h[4 * i + 0] = pack_h2(v0.x, v0.y);
    g_wm_h[4 * i + 1] = pack_h2(v0.z, v0.w);
    g_wm_h[4 * i + 2] = pack_h2(v1.x, v1.y);
    g_wm_h[4 * i + 3] = pack_h2(v1.z, v1.w);
}

// ---------------------------------------------------------------------------
// Kernel 1: wq[b][a] = query[b] . W_query[a]   (fp32 exact, tiny)
// ---------------------------------------------------------------------------
__global__ void wq_kernel(const float* __restrict__ query, const float* __restrict__ Wq) {
    int b = blockIdx.x, a = threadIdx.x;
    const float4* q4 = (const float4*)(query + b * NQ);
    const float4* w4 = (const float4*)(Wq + a * NQ);
    float s = 0.f;
#pragma unroll 8
    for (int k = 0; k < NQ / 4; k++) {
        float4 q = q4[k], w = w4[k];
        s += q.x * w.x + q.y * w.y + q.z * w.z + q.w * w.w;
    }
    g_wq[b * NA + a] = s;
}

// ---------------------------------------------------------------------------
// Kernel 2: fused fp16 mma.sync GEMM (64 x 512 x 1024) + Wv.tanh(wq+wm)
//           + exp (no max-subtract: |score| <= ||Wv||_1 ~ 22.6, overflow-safe)
//           + per-CTA unnormalized context partial (hidden behind tensor work)
// ---------------------------------------------------------------------------
__device__ __forceinline__ void issue_B(int c, uint32_t bbuf, int tid) {
    int k2 = c * (KC / 2);                    // uint offset within row
#pragma unroll
    for (int i = 0; i < 4; i++) {             // 512 rows x 4 x 16B
        int e = tid + i * 512;
        int row = e >> 2, c16 = e & 3;
        cpasync16(bbuf + (row * RS + c16 * 4) * 4,
                  g_wm_h + (size_t)row * (NM / 2) + k2 + c16 * 4);
    }
    asm volatile("cp.async.commit_group;" ::: "memory");
}

__global__ __launch_bounds__(512, 1) void score_kernel(
    const float* __restrict__ mem, const float* __restrict__ Wv,
    float* __restrict__ alpha_un)
{
    extern __shared__ __align__(16) uint32_t smem[];
    uint32_t sbase = smem_u32(smem);
    float* wqs = (float*)(smem + OFF_WQ);
    float* wvs = (float*)(smem + OFF_WV);
    float* spr = (float*)(smem + OFF_SP);
    float* es  = (float*)(smem + OFF_ES);

    int tid = threadIdx.x, wid = tid >> 5, lane = tid & 31;
    int g = lane >> 2, tg = lane & 3;
    int b = blockIdx.y, t0 = blockIdx.x * BM;

    for (int i = tid; i < NA; i += 512) {
        wqs[i] = g_wq[b * NA + i];
        wvs[i] = Wv[i];
    }

    const float* Ag = mem + ((size_t)b * NT + t0) * NM;
    const int arow = tid >> 3, ac4 = tid & 7;   // A: 64 rows x 8 float4

    // ldmatrix lane-address components (uint offsets within a stage)
    int q8 = lane >> 3, r8 = lane & 7;
    int aoff = ((q8 & 1) * 8 + r8) * RS + (q8 >> 1) * 4;
    int boff = ((q8 & 2) * 4 + r8 + wid * 32) * RS + (q8 & 1) * 4;

    float acc[4][4][4];
#pragma unroll
    for (int mf = 0; mf < 4; mf++)
#pragma unroll
        for (int j = 0; j < 4; j++)
#pragma unroll
            for (int qq = 0; qq < 4; qq++) acc[mf][j][qq] = 0.f;

    // prologue: A two chunks deep in regs; B three stages deep in smem
    float4 ar0 = *(const float4*)(Ag + (size_t)arow * NM + ac4 * 4);            // A(0)
    float4 ar1 = *(const float4*)(Ag + (size_t)arow * NM + KC + ac4 * 4);       // A(1)
    issue_B(0, sbase + (OFF_B + 0 * B_ST) * 4, tid);
    issue_B(1, sbase + (OFF_B + 1 * B_ST) * 4, tid);
    issue_B(2, sbase + (OFF_B + 2 * B_ST) * 4, tid);

    for (int c = 0; c < NCHUNK; c++) {
        // guarantee B(c) landed: committed = B0..B(c+2)  ->  allow 2 pending
        if (c < NCHUNK - 2)      asm volatile("cp.async.wait_group 2;" ::: "memory");
        else if (c < NCHUNK - 1) asm volatile("cp.async.wait_group 1;" ::: "memory");
        else                     asm volatile("cp.async.wait_group 0;" ::: "memory");
        // store A(c) from regs (fp16)
        {
            uint32_t* Ab = smem + OFF_A + (c & 1) * A_ST;
            uint2 u;
            u.x = pack_h2(ar0.x, ar0.y);
            u.y = pack_h2(ar0.z, ar0.w);
            *(uint2*)(Ab + arow * RS + ac4 * 2) = u;
        }
        __syncthreads();   // B(c)+A(c) visible; all warps done with stage (c-1)%4 and A(c-1)
        ar0 = ar1;
        if (c < NCHUNK - 2)
            ar1 = *(const float4*)(Ag + (size_t)arow * NM + (c + 2) * KC + ac4 * 4);
        if (c < NCHUNK - 3)
            issue_B(c + 3, sbase + (OFF_B + ((c + 3) % NBST) * B_ST) * 4, tid);

        uint32_t Abase = sbase + (OFF_A + (c & 1) * A_ST + aoff) * 4;
        uint32_t Bbase = sbase + (OFF_B + (c % NBST) * B_ST + boff) * 4;
#pragma unroll
        for (int ks = 0; ks < 2; ks++) {
            int ko4 = ks * 8 * 4;   // byte offset for this k16 step
            unsigned af[4][4];
#pragma unroll
            for (int mf = 0; mf < 4; mf++)
                LDMX4(af[mf][0], af[mf][1], af[mf][2], af[mf][3],
                      Abase + ko4 + mf * 16 * RS * 4);
            unsigned bf[8];
            LDMX4(bf[0], bf[1], bf[2], bf[3], Bbase + ko4);
            LDMX4(bf[4], bf[5], bf[6], bf[7], Bbase + ko4 + 16 * RS * 4);
#pragma unroll
            for (int j = 0; j < 4; j++) {
                unsigned b0 = bf[j * 2], b1 = bf[j * 2 + 1];
#pragma unroll
                for (int mf = 0; mf < 4; mf++)
                    mma_f16(acc[mf][j][0], acc[mf][j][1], acc[mf][j][2], acc[mf][j][3],
                            af[mf][0], af[mf][1], af[mf][2], af[mf][3], b0, b1);
            }
        }
    }

    // epilogue 1: partial score rows for this warp's 32 cols
    float p0[4], p1[4];
#pragma unroll
    for (int mf = 0; mf < 4; mf++) { p0[mf] = 0.f; p1[mf] = 0.f; }
#pragma unroll
    for (int mf = 0; mf < 4; mf++)
#pragma unroll
        for (int j = 0; j < 4; j++) {
            int a0 = wid * 32 + j * 8 + 2 * tg;
            float w0 = wvs[a0], w1 = wvs[a0 + 1];
            float q0 = wqs[a0], q1 = wqs[a0 + 1];
            p0[mf] += w0 * tanhf(q0 + acc[mf][j][0]) + w1 * tanhf(q1 + acc[mf][j][1]);
            p1[mf] += w0 * tanhf(q0 + acc[mf][j][2]) + w1 * tanhf(q1 + acc[mf][j][3]);
        }
#pragma unroll
    for (int mf = 0; mf < 4; mf++) {
        p0[mf] += __shfl_xor_sync(0xffffffffu, p0[mf], 1);
        p0[mf] += __shfl_xor_sync(0xffffffffu, p0[mf], 2);
        p1[mf] += __shfl_xor_sync(0xffffffffu, p1[mf], 1);
        p1[mf] += __shfl_xor_sync(0xffffffffu, p1[mf], 2);
    }
    if (tg == 0) {
#pragma unroll
        for (int mf = 0; mf < 4; mf++) {
            spr[wid * 64 + mf * 16 + g]     = p0[mf];
            spr[wid * 64 + mf * 16 + 8 + g] = p1[mf];
        }
    }
    __syncthreads();
    if (tid < BM) {
        float s = 0.f;
#pragma unroll
        for (int w = 0; w < 16; w++) s += spr[w * 64 + tid];
        float e = expf(s);                       // no max-subtract: bounded
        alpha_un[b * NT + t0 + tid] = e;
        es[tid] = e;
    }
    __syncthreads();

    // epilogue 2: unnormalized context partial for this 64-row slice
    {
        int m = tid * 2;                          // 512 threads x float2 = 1024 cols
        const float* mp = mem + ((size_t)b * NT + t0) * NM + m;
        float cx = 0.f, cy = 0.f;
#pragma unroll 8
        for (int t = 0; t < BM; t++) {
            float e = es[t];
            float2 v = *(const float2*)(mp + (size_t)t * NM);
            cx += e * v.x;
            cy += e * v.y;
        }
        float2 out; out.x = cx; out.y = cy;
        *(float2*)(g_ctxp + ((size_t)blockIdx.x * NB + b) * NM + m) = out;
    }
}

// ---------------------------------------------------------------------------
// Kernel 3: finalize per batch row: Z, alpha normalize, context reduce
// ---------------------------------------------------------------------------
__global__ __launch_bounds__(256) void finalize_kernel(
    float* __restrict__ alpha, float* __restrict__ ctx)
{
    __shared__ float red[8];
    int b = blockIdx.x, tid = threadIdx.x;
    float* arow = alpha + b * NT;

    float z = 0.f;
#pragma unroll
    for (int i = 0; i < NT / 256; i++) z += arow[tid + 256 * i];
#pragma unroll
    for (int o = 16; o; o >>= 1) z += __shfl_xor_sync(0xffffffffu, z, o);
    if ((tid & 31) == 0) red[tid >> 5] = z;
    __syncthreads();
    z = 0.f;
#pragma unroll
    for (int w = 0; w < 8; w++) z += red[w];
    float inv = 1.f / z;

#pragma unroll
    for (int i = 0; i < NT / 256; i++) arow[tid + 256 * i] *= inv;

    // context: 256 threads x float4 = 1024 cols; reduce 32 slices
    int m = tid * 4;
    float4 s = {0.f, 0.f, 0.f, 0.f};
#pragma unroll 4
    for (int sl = 0; sl < NSLICE; sl++) {
        float4 v = *(const float4*)(g_ctxp + ((size_t)sl * NB + b) * NM + m);
        s.x += v.x; s.y += v.y; s.z += v.z; s.w += v.w;
    }
    s.x *= inv; s.y *= inv; s.z *= inv; s.w *= inv;
    *(float4*)(ctx + b * NM + m) = s;
}

// ---------------------------------------------------------------------------
extern "C" void kernel_launch(void* const* d_in, const int* in_sizes, int n_in,
                              void* d_out, int out_size) {
    const float* query  = (const float*)d_in[0];
    const float* memory = (const float*)d_in[1];
    const float* Wq     = (const float*)d_in[2];
    const float* Wm     = (const float*)d_in[3];
    const float* Wv     = (const float*)d_in[4];
    float* alpha = (float*)d_out;            // [64, 2048]
    float* ctx   = alpha + NB * NT;          // [64, 1024]

    cvt_wm_kernel<<<256, 256>>>(Wm);
    wq_kernel<<<NB, NA>>>(query, Wq);

    cudaFuncSetAttribute(score_kernel, cudaFuncAttributeMaxDynamicSharedMemorySize, SMEM_SZ);
    score_kernel<<<dim3(NSLICE, NB), 512, SMEM_SZ>>>(memory, Wv, alpha);

    finalize_kernel<<<NB, 256>>>(alpha, ctx);
}

// round 10
// speedup vs baseline: 2.3014x; 1.2275x over previous
#include <cuda_runtime.h>
#include <cuda_fp16.h>
#include <cstdint>

#define NB 64
#define NT 2048
#define NM 1024
#define NA 512
#define NQ 1024

#define BM 64             // t-rows per CTA
#define KC 64             // k per stage (fp16: 4 MMA k-steps)
#define NCHUNK (NM / KC)  // 16
#define RS 36             // smem row stride in uints: conflict-free (shift 4/row), 16B-aligned
#define NBST 2            // B stages

#define A_ST (BM * RS)                   // 2304 uints per A stage
#define B_ST (NA * RS)                   // 18432 uints per B stage
#define OFF_A 0
#define OFF_B (2 * A_ST)                 // 4608
#define OFF_WQ (OFF_B + NBST * B_ST)     // floats from here
#define OFF_WV (OFF_WQ + NA)
#define OFF_SP (OFF_WV + NA)
#define OFF_ES (OFF_SP + 16 * 64)        // 64 exp(score) values
#define SMEM_WORDS (OFF_ES + 64)
#define SMEM_SZ (SMEM_WORDS * 4)         // ~171 KB

#define NSLICE (NT / BM)                 // 32 t-slices per batch

__device__ float g_wq[NB * NA];
__device__ uint32_t g_wm_h[NA * NM / 2];        // Wm as half2 pairs, [a][k/2]
__device__ float g_ctxp[NSLICE * NB * NM];      // context partials [slice][b][m] (8 MB)

__device__ __forceinline__ uint32_t smem_u32(const void* p) {
    uint32_t a;
    asm("{ .reg .u64 t; cvta.to.shared.u64 t, %1; cvt.u32.u64 %0, t; }" : "=r"(a) : "l"(p));
    return a;
}

__device__ __forceinline__ void cpasync16(uint32_t dst, const void* src) {
    asm volatile("cp.async.cg.shared.global [%0], [%1], 16;" :: "r"(dst), "l"(src) : "memory");
}

__device__ __forceinline__ uint32_t pack_h2(float x, float y) {
    __half2 h = __floats2half2_rn(x, y);
    return *(uint32_t*)&h;
}

__device__ __forceinline__ void mma_f16(float& d0, float& d1, float& d2, float& d3,
                                        unsigned a0, unsigned a1, unsigned a2, unsigned a3,
                                        unsigned b0, unsigned b1) {
    asm("mma.sync.aligned.m16n8k16.row.col.f32.f16.f16.f32 "
        "{%0,%1,%2,%3},{%4,%5,%6,%7},{%8,%9},{%0,%1,%2,%3};"
        : "+f"(d0), "+f"(d1), "+f"(d2), "+f"(d3)
        : "r"(a0), "r"(a1), "r"(a2), "r"(a3), "r"(b0), "r"(b1));
}

#define LDMX4(r0, r1, r2, r3, addr) \
    asm volatile("ldmatrix.sync.aligned.m8n8.x4.shared.b16 {%0,%1,%2,%3}, [%4];" \
                 : "=r"(r0), "=r"(r1), "=r"(r2), "=r"(r3) : "r"(addr))

// ---------------------------------------------------------------------------
// Kernel 0: convert Wm (fp32) -> g_wm_h (half2 pairs)
// ---------------------------------------------------------------------------
__global__ void cvt_wm_kernel(const float* __restrict__ Wm) {
    int i = blockIdx.x * 256 + threadIdx.x;
    const float4* s = (const float4*)Wm;
    float4 v0 = s[2 * i], v1 = s[2 * i + 1];
    g_wm_h[4 * i + 0] = pack_h2(v0.x, v0.y);
    g_wm_h[4 * i + 1] = pack_h2(v0.z, v0.w);
    g_wm_h[4 * i + 2] = pack_h2(v1.x, v1.y);
    g_wm_h[4 * i + 3] = pack_h2(v1.z, v1.w);
}

// ---------------------------------------------------------------------------
// Kernel 1: wq[b][a] = query[b] . W_query[a]  (fp32 exact; 256 CTAs x 128 thr)
// ---------------------------------------------------------------------------
__global__ __launch_bounds__(128) void wq_kernel(
    const float* __restrict__ query, const float* __restrict__ Wq)
{
    int b = blockIdx.y, a = blockIdx.x * 128 + threadIdx.x;
    const float4* q4 = (const float4*)(query + b * NQ);
    const float4* w4 = (const float4*)(Wq + a * NQ);
    float s = 0.f;
#pragma unroll 8
    for (int k = 0; k < NQ / 4; k++) {
        float4 q = q4[k], w = w4[k];
        s += q.x * w.x + q.y * w.y + q.z * w.z + q.w * w.w;
    }
    g_wq[b * NA + a] = s;
}

// ---------------------------------------------------------------------------
// Kernel 2: fused fp16 mma.sync GEMM (64 x 512 x 1024) + Wv.tanh(wq+wm)
//           + exp + unnormalized context partial.
// KC=64: 16 chunks, half the barrier/ladder overhead. Single-depth B pipeline:
// B(c+1) issued after the barrier of chunk c into the buffer freed by that
// barrier; wait_group 0 at top of each chunk drains it (one chunk of cover).
// ---------------------------------------------------------------------------
__device__ __forceinline__ void issue_B(int c, uint32_t bbuf, int tid) {
    int k2 = c * (KC / 2);                    // uint offset within row
#pragma unroll
    for (int i = 0; i < 8; i++) {             // 512 rows x 8 x 16B = 64KB
        int e = tid + i * 512;
        int row = e >> 3, c16 = e & 7;
        cpasync16(bbuf + (row * RS + c16 * 4) * 4,
                  g_wm_h + (size_t)row * (NM / 2) + k2 + c16 * 4);
    }
    asm volatile("cp.async.commit_group;" ::: "memory");
}

__global__ __launch_bounds__(512, 1) void score_kernel(
    const float* __restrict__ mem, const float* __restrict__ Wv,
    float* __restrict__ alpha_un)
{
    extern __shared__ __align__(16) uint32_t smem[];
    uint32_t sbase = smem_u32(smem);
    float* wqs = (float*)(smem + OFF_WQ);
    float* wvs = (float*)(smem + OFF_WV);
    float* spr = (float*)(smem + OFF_SP);
    float* es  = (float*)(smem + OFF_ES);

    int tid = threadIdx.x, wid = tid >> 5, lane = tid & 31;
    int g = lane >> 2, tg = lane & 3;
    int b = blockIdx.y, t0 = blockIdx.x * BM;

    for (int i = tid; i < NA; i += 512) {
        wqs[i] = g_wq[b * NA + i];
        wvs[i] = Wv[i];
    }

    const float* Ag = mem + ((size_t)b * NT + t0) * NM;
    const int arow = tid >> 3, ac = tid & 7;   // A: 64 rows x 8 float4-pairs

    // ldmatrix lane-address components (uint offsets within a stage)
    int q8 = lane >> 3, r8 = lane & 7;
    int aoff = ((q8 & 1) * 8 + r8) * RS + (q8 >> 1) * 4;
    int boff = ((q8 & 2) * 4 + r8 + wid * 32) * RS + (q8 & 1) * 4;

    float acc[4][4][4];
#pragma unroll
    for (int mf = 0; mf < 4; mf++)
#pragma unroll
        for (int j = 0; j < 4; j++)
#pragma unroll
            for (int qq = 0; qq < 4; qq++) acc[mf][j][qq] = 0.f;

    // prologue: A(0) in regs; B(0) in flight
    float4 ar0 = *(const float4*)(Ag + (size_t)arow * NM + ac * 8);
    float4 ar1 = *(const float4*)(Ag + (size_t)arow * NM + ac * 8 + 4);
    issue_B(0, sbase + (OFF_B + 0 * B_ST) * 4, tid);

    for (int c = 0; c < NCHUNK; c++) {
        asm volatile("cp.async.wait_group 0;" ::: "memory");   // B(c) landed
        // store A(c) from regs (fp16, 8 cols -> uint4)
        {
            uint32_t* Ab = smem + OFF_A + (c & 1) * A_ST;
            uint4 u;
            u.x = pack_h2(ar0.x, ar0.y);
            u.y = pack_h2(ar0.z, ar0.w);
            u.z = pack_h2(ar1.x, ar1.y);
            u.w = pack_h2(ar1.z, ar1.w);
            *(uint4*)(Ab + arow * RS + ac * 4) = u;
        }
        __syncthreads();   // B(c)+A(c) visible; buf (c+1)&1 fully consumed
        if (c < NCHUNK - 1) {
            issue_B(c + 1, sbase + (OFF_B + ((c + 1) & 1) * B_ST) * 4, tid);
            int k0 = (c + 1) * KC;
            ar0 = *(const float4*)(Ag + (size_t)arow * NM + k0 + ac * 8);
            ar1 = *(const float4*)(Ag + (size_t)arow * NM + k0 + ac * 8 + 4);
        }

        uint32_t Abase = sbase + (OFF_A + (c & 1) * A_ST + aoff) * 4;
        uint32_t Bbase = sbase + (OFF_B + (c & 1) * B_ST + boff) * 4;
#pragma unroll
        for (int ks = 0; ks < 4; ks++) {
            int ko4 = ks * 8 * 4;   // byte offset for this k16 step
            unsigned af[4][4];
#pragma unroll
            for (int mf = 0; mf < 4; mf++)
                LDMX4(af[mf][0], af[mf][1], af[mf][2], af[mf][3],
                      Abase + ko4 + mf * 16 * RS * 4);
            unsigned bf[8];
            LDMX4(bf[0], bf[1], bf[2], bf[3], Bbase + ko4);
            LDMX4(bf[4], bf[5], bf[6], bf[7], Bbase + ko4 + 16 * RS * 4);
#pragma unroll
            for (int j = 0; j < 4; j++) {
                unsigned b0 = bf[j * 2], b1 = bf[j * 2 + 1];
#pragma unroll
                for (int mf = 0; mf < 4; mf++)
                    mma_f16(acc[mf][j][0], acc[mf][j][1], acc[mf][j][2], acc[mf][j][3],
                            af[mf][0], af[mf][1], af[mf][2], af[mf][3], b0, b1);
            }
        }
    }

    // epilogue 1: partial score rows for this warp's 32 cols
    float p0[4], p1[4];
#pragma unroll
    for (int mf = 0; mf < 4; mf++) { p0[mf] = 0.f; p1[mf] = 0.f; }
#pragma unroll
    for (int mf = 0; mf < 4; mf++)
#pragma unroll
        for (int j = 0; j < 4; j++) {
            int a0 = wid * 32 + j * 8 + 2 * tg;
            float w0 = wvs[a0], w1 = wvs[a0 + 1];
            float q0 = wqs[a0], q1 = wqs[a0 + 1];
            p0[mf] += w0 * tanhf(q0 + acc[mf][j][0]) + w1 * tanhf(q1 + acc[mf][j][1]);
            p1[mf] += w0 * tanhf(q0 + acc[mf][j][2]) + w1 * tanhf(q1 + acc[mf][j][3]);
        }
#pragma unroll
    for (int mf = 0; mf < 4; mf++) {
        p0[mf] += __shfl_xor_sync(0xffffffffu, p0[mf], 1);
        p0[mf] += __shfl_xor_sync(0xffffffffu, p0[mf], 2);
        p1[mf] += __shfl_xor_sync(0xffffffffu, p1[mf], 1);
        p1[mf] += __shfl_xor_sync(0xffffffffu, p1[mf], 2);
    }
    if (tg == 0) {
#pragma unroll
        for (int mf = 0; mf < 4; mf++) {
            spr[wid * 64 + mf * 16 + g]     = p0[mf];
            spr[wid * 64 + mf * 16 + 8 + g] = p1[mf];
        }
    }
    __syncthreads();
    if (tid < BM) {
        float s = 0.f;
#pragma unroll
        for (int w = 0; w < 16; w++) s += spr[w * 64 + tid];
        float e = expf(s);                       // no max-subtract: bounded
        alpha_un[b * NT + t0 + tid] = e;
        es[tid] = e;
    }
    __syncthreads();

    // epilogue 2: unnormalized context partial; t split across thread halves
    {
        float* pp = (float*)(smem + OFF_B);       // reuse B region (4KB)
        int half = tid >> 8;                       // 0: t<32, 1: t>=32
        int m = (tid & 255) * 4;
        const float* mp = mem + ((size_t)b * NT + t0 + half * 32) * NM + m;
        float4 cacc = {0.f, 0.f, 0.f, 0.f};
#pragma unroll 8
        for (int t = 0; t < 32; t++) {
            float e = es[half * 32 + t];
            float4 v = *(const float4*)(mp + (size_t)t * NM);
            cacc.x += e * v.x; cacc.y += e * v.y;
            cacc.z += e * v.z; cacc.w += e * v.w;
        }
        if (half) *(float4*)(pp + m) = cacc;
        __syncthreads();
        if (!half) {
            float4 o = *(const float4*)(pp + m);
            o.x += cacc.x; o.y += cacc.y; o.z += cacc.z; o.w += cacc.w;
            *(float4*)(g_ctxp + ((size_t)blockIdx.x * NB + b) * NM + m) = o;
        }
    }
}

// ---------------------------------------------------------------------------
// Kernel 3: finalize per batch row: Z, alpha normalize, context reduce
// ---------------------------------------------------------------------------
__global__ __launch_bounds__(256) void finalize_kernel(
    float* __restrict__ alpha, float* __restrict__ ctx)
{
    __shared__ float red[8];
    int b = blockIdx.x, tid = threadIdx.x;
    float* arow = alpha + b * NT;

    float z = 0.f;
#pragma unroll
    for (int i = 0; i < NT / 256; i++) z += arow[tid + 256 * i];
#pragma unroll
    for (int o = 16; o; o >>= 1) z += __shfl_xor_sync(0xffffffffu, z, o);
    if ((tid & 31) == 0) red[tid >> 5] = z;
    __syncthreads();
    z = 0.f;
#pragma unroll
    for (int w = 0; w < 8; w++) z += red[w];
    float inv = 1.f / z;

#pragma unroll
    for (int i = 0; i < NT / 256; i++) arow[tid + 256 * i] *= inv;

    // context: 256 threads x float4 = 1024 cols; reduce 32 slices
    int m = tid * 4;
    float4 s = {0.f, 0.f, 0.f, 0.f};
#pragma unroll 4
    for (int sl = 0; sl < NSLICE; sl++) {
        float4 v = *(const float4*)(g_ctxp + ((size_t)sl * NB + b) * NM + m);
        s.x += v.x; s.y += v.y; s.z += v.z; s.w += v.w;
    }
    s.x *= inv; s.y *= inv; s.z *= inv; s.w *= inv;
    *(float4*)(ctx + b * NM + m) = s;
}

// ---------------------------------------------------------------------------
extern "C" void kernel_launch(void* const* d_in, const int* in_sizes, int n_in,
                              void* d_out, int out_size) {
    const float* query  = (const float*)d_in[0];
    const float* memory = (const float*)d_in[1];
    const float* Wq     = (const float*)d_in[2];
    const float* Wm     = (const float*)d_in[3];
    const float* Wv     = (const float*)d_in[4];
    float* alpha = (float*)d_out;            // [64, 2048]
    float* ctx   = alpha + NB * NT;          // [64, 1024]

    cvt_wm_kernel<<<256, 256>>>(Wm);
    wq_kernel<<<dim3(4, NB), 128>>>(query, Wq);

    cudaFuncSetAttribute(score_kernel, cudaFuncAttributeMaxDynamicSharedMemorySize, SMEM_SZ);
    score_kernel<<<dim3(NSLICE, NB), 512, SMEM_SZ>>>(memory, Wv, alpha);

    finalize_kernel<<<NB, 256>>>(alpha, ctx);
}